// round 13
// baseline (speedup 1.0000x reference)
#include <cuda_runtime.h>
#include <cuda_bf16.h>
#include <cstdint>

// Problem constants
#define CC      128
#define GROUPS  8
#define NB      4
#define NN      8192
#define MM      32768
#define KNN     16
#define NROWS   (NB*NN)
#define TROWS   64                   // rows per CTA tile
#define THREADS 256
#define CNT_INV (1.0f/131072.0f)
#define APAD    136                  // padded bf16 row stride (272B -> conflict-free ldmatrix)

// layer-kernel smem: A tiles only
#define SM_AH   0
#define SM_AL   (TROWS*APAD*2)             // 17408
#define SMEM_DYN (2*TROWS*APAD*2)          // 34816

// prep smem: 64 n-rows x APAD bf16
#define SMEM_P  (64*APAD*2)                // 17408

// Scratch (device globals; no cudaMalloc allowed)
__device__ __align__(16) uint4 g_Wfrag[3][2][8][8][32];    // [layer][hi/lo][t][nb16][lane]
__device__ float g_sum[3][NB*GROUPS];
__device__ float g_sqs[3][NB*GROUPS];
__device__ float g_buf0[NROWS*CC];
__device__ float g_buf1[NROWS*CC];

// ---------------------------------------------------------------------------
// Helpers (all plain sm_80+ features; NO 'a'-gated instructions)
// ---------------------------------------------------------------------------
__device__ __forceinline__ uint32_t cvta_smem(const void* p) {
    uint32_t a;
    asm("{ .reg .u64 t; cvta.to.shared.u64 t, %1; cvt.u32.u64 %0, t; }"
        : "=r"(a) : "l"(p));
    return a;
}
__device__ __forceinline__ void ldmx4(uint32_t addr, uint32_t r[4]) {
    asm volatile("ldmatrix.sync.aligned.m8n8.x4.shared.b16 {%0,%1,%2,%3}, [%4];"
        : "=r"(r[0]), "=r"(r[1]), "=r"(r[2]), "=r"(r[3]) : "r"(addr));
}
// non-volatile: pure register op; lets ptxas schedule freely
__device__ __forceinline__ void mma16816(float d[4], const uint32_t a[4],
                                         uint32_t b0, uint32_t b1) {
    asm("mma.sync.aligned.m16n8k16.row.col.f32.bf16.bf16.f32 "
        "{%0,%1,%2,%3}, {%4,%5,%6,%7}, {%8,%9}, {%0,%1,%2,%3};"
        : "+f"(d[0]), "+f"(d[1]), "+f"(d[2]), "+f"(d[3])
        : "r"(a[0]), "r"(a[1]), "r"(a[2]), "r"(a[3]), "r"(b0), "r"(b1));
}
#define STS16(a, v) \
    asm volatile("st.shared.b16 [%0], %1;" :: "r"(a), "h"(v) : "memory")
#define STS64(a, x, y) \
    asm volatile("st.shared.v2.b32 [%0], {%1,%2};" :: "r"(a), "r"(x), "r"(y) : "memory")
#define PAIR_BAR(id) \
    asm volatile("bar.sync %0, 64;" :: "r"(id) : "memory")

__device__ __forceinline__ float leaky(float h) { return h >= 0.0f ? h : 0.1f * h; }

// ---------------------------------------------------------------------------
// prep: zero stats; block (l, h, nh) handles n in [nh*64, nh*64+64):
// split W^T into smem bf16 tile (float4 reads), fragmentize via the exact
// ldmatrix sequence the GEMM uses. 12 blocks.
// ---------------------------------------------------------------------------
__global__ void prep_kernel(const float* __restrict__ W1,
                            const float* __restrict__ W2,
                            const float* __restrict__ W3) {
    extern __shared__ __align__(16) char smem[];
    const int tid  = threadIdx.x;
    const int wid  = tid >> 5;
    const int lane = tid & 31;
    const int l  = blockIdx.x >> 2;
    const int h  = (blockIdx.x >> 1) & 1;
    const int nh = blockIdx.x & 1;          // which 64-col half of n
    const uint32_t sb = cvta_smem(smem);

    if (blockIdx.x == 0) {
        if (tid < 96)        { g_sum[tid / 32][tid % 32] = 0.0f; }
        else if (tid < 192)  { int u = tid - 96; g_sqs[u / 32][u % 32] = 0.0f; }
    }

    const float* W = (l == 0) ? W1 : ((l == 1) ? W2 : W3);

    // read W[k][n4] as float4 (n fast), split, scatter bf16 to smem[(n-nh*64)*APAD + k]
    #pragma unroll
    for (int t = 0; t < 8; t++) {
        int idx = tid + t * THREADS;       // 2048 float4 jobs
        int k   = idx >> 4;                // 16 float4 per 64-col half-row
        int n4  = (idx & 15) * 4 + nh * 64;
        float4 v = *(const float4*)&W[k * CC + n4];
        float vv[4] = {v.x, v.y, v.z, v.w};
        #pragma unroll
        for (int u = 0; u < 4; u++) {
            __nv_bfloat16 hi = __float2bfloat16(vv[u]);
            __nv_bfloat16 val = h == 0 ? hi
                              : __float2bfloat16(vv[u] - __bfloat162float(hi));
            STS16(sb + (uint32_t)((n4 + u - nh * 64) * APAD + k) * 2,
                  __bfloat16_as_ushort(val));
        }
    }
    __syncthreads();

    // 32 jobs: (t, nb_local 0..3); 4 per warp. Same lane addressing as the GEMM.
    const uint32_t lrow = (uint32_t)((lane & 7) + ((lane >> 4) << 3));
    const uint32_t lcol = (uint32_t)(lane & 8) << 1;
    #pragma unroll
    for (int i = 0; i < 4; i++) {
        int job = wid * 4 + i;
        int t   = job & 7;
        int nbl = job >> 3;                 // 0..3
        uint32_t addr = sb + (((uint32_t)(nbl * 16) + lrow) * APAD) * 2 + lcol
                      + (uint32_t)t * 32;
        uint32_t r[4];
        ldmx4(addr, r);
        g_Wfrag[l][h][t][nh * 4 + nbl][lane] = make_uint4(r[0], r[1], r[2], r[3]);
    }
}

// ---------------------------------------------------------------------------
// Fused layer kernel: 64-row tile, HMMA bf16 3-term-split GEMM.
// NO block-wide barriers: warp pair (w, w+4) builds & consumes its own
// 16-row m-strip, synchronized by a named pair barrier (id 1+pair, 64 thr).
// GN stats/gamma/beta loaded per-warp from global; group stats flushed via
// per-warp shuffle reduction + lane-0 global atomicAdd (REDG).
// MODE 0: x = IDW gather   MODE 1: x = leaky(GN(prev))   MODE 2: +resid
// ---------------------------------------------------------------------------
template <int MODE>
__global__ __launch_bounds__(THREADS, 4)
void layer_kernel(const float* __restrict__ in_y,
                  const float* __restrict__ resid,
                  const float* __restrict__ s_feats,
                  const float* __restrict__ q_points,
                  const float* __restrict__ s_points,
                  const int*   __restrict__ nbr_idx,
                  const float* __restrict__ bias,
                  const float* __restrict__ gamma_prev,
                  const float* __restrict__ beta_prev,
                  int layer,
                  float* __restrict__ out_y) {
    extern __shared__ __align__(16) char smem[];

    const int tid  = threadIdx.x;
    const int wid  = tid >> 5;
    const int lane = tid & 31;
    const int row0 = blockIdx.x * TROWS;
    const int b    = row0 >> 13;

    const int pair = wid & 3;            // m-strip id
    const int half = wid >> 2;           // n-half id
    const int mbase = pair * 16;

    const uint32_t sb = cvta_smem(smem);

    // ---- Stage A: warp builds its 8 rows of the pair strip ----
    // rows r = mbase + half*8 + it; lane owns col quad c4 = lane*4
    {
        const int c4 = lane * 4;
        float m = 0.f, rs = 0.f;
        float4 gm, bt;
        if (MODE != 0) {
            int g = lane >> 2;
            float s  = g_sum[layer - 1][b * GROUPS + g];
            float s2 = g_sqs[layer - 1][b * GROUPS + g];
            m  = s * CNT_INV;
            rs = rsqrtf(s2 * CNT_INV - m * m + 1e-5f);
            gm = *(const float4*)&gamma_prev[c4];
            bt = *(const float4*)&beta_prev[c4];
        }
        #pragma unroll
        for (int it = 0; it < 8; it++) {
            int r = mbase + half * 8 + it;
            float4 x;
            if (MODE == 0) {
                int n    = (row0 + r) & (NN - 1);
                int base = b * NN + n;
                // lane-parallel: lane k<16 owns neighbor k
                float w = 0.0f;
                int   id = 0;
                {
                    float qx = q_points[base * 3 + 0];
                    float qy = q_points[base * 3 + 1];
                    float qz = q_points[base * 3 + 2];
                    if (lane < KNN) {
                        const float* sp = s_points + ((size_t)base * KNN + lane) * 3;
                        float dx = sp[0] - qx, dy = sp[1] - qy, dz = sp[2] - qz;
                        w  = 1.0f / (dx * dx + dy * dy + dz * dz + 1e-8f);
                        id = nbr_idx[base * KNN + lane];
                    }
                }
                float wsum = w;
                #pragma unroll
                for (int o = 16; o > 0; o >>= 1)
                    wsum += __shfl_xor_sync(0xffffffffu, wsum, o);
                float inv = 1.0f / wsum;
                x = make_float4(0.f, 0.f, 0.f, 0.f);
                #pragma unroll
                for (int k = 0; k < KNN; k++) {
                    float wk  = __shfl_sync(0xffffffffu, w,  k);
                    int   idk = __shfl_sync(0xffffffffu, id, k);
                    const float4* fr = (const float4*)(s_feats + ((size_t)(b * MM + idk)) * CC);
                    float4 v = fr[lane];
                    x.x += wk * v.x; x.y += wk * v.y;
                    x.z += wk * v.z; x.w += wk * v.w;
                }
                x.x *= inv; x.y *= inv; x.z *= inv; x.w *= inv;
            } else {
                float4 v = *(const float4*)&in_y[(size_t)(row0 + r) * CC + c4];
                x.x = leaky((v.x - m) * rs * gm.x + bt.x);
                x.y = leaky((v.y - m) * rs * gm.y + bt.y);
                x.z = leaky((v.z - m) * rs * gm.z + bt.z);
                x.w = leaky((v.w - m) * rs * gm.w + bt.w);
                if (MODE == 2) {
                    float4 q = *(const float4*)&resid[(size_t)(row0 + r) * CC + c4];
                    x.x += q.x; x.y += q.y; x.z += q.z; x.w += q.w;
                }
            }
            __nv_bfloat16 h0 = __float2bfloat16(x.x);
            __nv_bfloat16 h1 = __float2bfloat16(x.y);
            __nv_bfloat16 h2 = __float2bfloat16(x.z);
            __nv_bfloat16 h3 = __float2bfloat16(x.w);
            __nv_bfloat16 l0 = __float2bfloat16(x.x - __bfloat162float(h0));
            __nv_bfloat16 l1 = __float2bfloat16(x.y - __bfloat162float(h1));
            __nv_bfloat16 l2 = __float2bfloat16(x.z - __bfloat162float(h2));
            __nv_bfloat16 l3 = __float2bfloat16(x.w - __bfloat162float(h3));
            uint32_t ha = (uint32_t)__bfloat16_as_ushort(h0) | ((uint32_t)__bfloat16_as_ushort(h1) << 16);
            uint32_t hb = (uint32_t)__bfloat16_as_ushort(h2) | ((uint32_t)__bfloat16_as_ushort(h3) << 16);
            uint32_t la = (uint32_t)__bfloat16_as_ushort(l0) | ((uint32_t)__bfloat16_as_ushort(l1) << 16);
            uint32_t lb = (uint32_t)__bfloat16_as_ushort(l2) | ((uint32_t)__bfloat16_as_ushort(l3) << 16);
            uint32_t off = (uint32_t)(r * APAD + c4) * 2;
            STS64(sb + SM_AH + off, ha, hb);
            STS64(sb + SM_AL + off, la, lb);
        }
    }

    // pair barrier: wait only for the partner warp that built the other 8 rows
    PAIR_BAR(1 + pair);

    // ---- HMMA GEMM: warp tile m16 x n64, 3-term split; B frags via LDG ----
    const int nb0 = half * 4;            // first n16 fragment index

    float acc[8][4];
    #pragma unroll
    for (int j = 0; j < 8; j++)
        #pragma unroll
        for (int q = 0; q < 4; q++) acc[j][q] = 0.0f;

    const uint32_t aoff = sb + SM_AH +
        (uint32_t)(((mbase + (lane & 15)) * APAD + ((lane >> 4) << 3)) << 1);

    const uint4* __restrict__ wfh = &g_Wfrag[layer][0][0][0][lane];
    const uint4* __restrict__ wfl = &g_Wfrag[layer][1][0][0][lane];

    #pragma unroll
    for (int t = 0; t < 8; t++) {
        const uint32_t ka = (uint32_t)t * 32;
        uint32_t ah[4], al[4];
        ldmx4(aoff + ka, ah);
        ldmx4(aoff + ka + SM_AL, al);
        #pragma unroll
        for (int p = 0; p < 4; p++) {
            const int fidx = (t * 8 + nb0 + p) * 32;
            uint4 bh = __ldg(wfh + fidx);
            uint4 bl = __ldg(wfl + fidx);
            float* a0 = acc[2 * p];
            float* a1 = acc[2 * p + 1];
            mma16816(a0, ah, bh.x, bh.y);
            mma16816(a1, ah, bh.z, bh.w);
            mma16816(a0, al, bh.x, bh.y);
            mma16816(a1, al, bh.z, bh.w);
            mma16816(a0, ah, bl.x, bl.y);
            mma16816(a1, ah, bl.z, bl.w);
        }
    }

    // ---- Epilogue: bias + store, shuffle-reduced stats -> global REDG ----
    {
        const int r0g   = row0 + mbase + (lane >> 2);
        const int nbase = half * 64;
        #pragma unroll
        for (int gj = 0; gj < 4; gj++) {
            float s = 0.0f, s2 = 0.0f;
            #pragma unroll
            for (int jj = 0; jj < 2; jj++) {
                int j = 2 * gj + jj;
                int c = nbase + 8 * j + (lane & 3) * 2;
                float bb0 = __ldg(&bias[c]);
                float bb1 = __ldg(&bias[c + 1]);
                float y00 = acc[j][0] + bb0;
                float y01 = acc[j][1] + bb1;
                float y10 = acc[j][2] + bb0;
                float y11 = acc[j][3] + bb1;
                *(float2*)&out_y[(size_t)r0g * CC + c]       = make_float2(y00, y01);
                *(float2*)&out_y[(size_t)(r0g + 8) * CC + c] = make_float2(y10, y11);
                s  += y00 + y01 + y10 + y11;
                s2 += y00 * y00 + y01 * y01 + y10 * y10 + y11 * y11;
            }
            #pragma unroll
            for (int o = 16; o > 0; o >>= 1) {
                s  += __shfl_xor_sync(0xffffffffu, s,  o);
                s2 += __shfl_xor_sync(0xffffffffu, s2, o);
            }
            if (lane == 0) {
                int g = (nbase >> 4) + gj;
                atomicAdd(&g_sum[layer][b * GROUPS + g], s);
                atomicAdd(&g_sqs[layer][b * GROUPS + g], s2);
            }
        }
    }
}

// ---------------------------------------------------------------------------
// Finalize: out = leaky(GN3(y3))
// ---------------------------------------------------------------------------
__global__ void finalize_kernel(const float* __restrict__ in_y,
                                const float* __restrict__ gamma,
                                const float* __restrict__ beta,
                                float* __restrict__ out) {
    int f  = blockIdx.x * blockDim.x + threadIdx.x;
    int e  = f * 4;
    int c4 = e & (CC - 1);
    int row = e >> 7;
    int b  = row >> 13;
    int g  = c4 >> 4;
    float s  = g_sum[2][b * GROUPS + g];
    float s2 = g_sqs[2][b * GROUPS + g];
    float m  = s * CNT_INV;
    float v  = s2 * CNT_INV - m * m;
    float rs = rsqrtf(v + 1e-5f);
    float4 x = *(const float4*)&in_y[e];
    float4 o;
    o.x = leaky((x.x - m) * rs * gamma[c4 + 0] + beta[c4 + 0]);
    o.y = leaky((x.y - m) * rs * gamma[c4 + 1] + beta[c4 + 1]);
    o.z = leaky((x.z - m) * rs * gamma[c4 + 2] + beta[c4 + 2]);
    o.w = leaky((x.w - m) * rs * gamma[c4 + 3] + beta[c4 + 3]);
    *(float4*)&out[e] = o;
}

// ---------------------------------------------------------------------------
extern "C" void kernel_launch(void* const* d_in, const int* in_sizes, int n_in,
                              void* d_out, int out_size) {
    const float* q_feats  = (const float*)d_in[0];
    const float* s_feats  = (const float*)d_in[1];
    const float* q_points = (const float*)d_in[2];
    const float* s_points = (const float*)d_in[3];
    const int*   nbr_idx  = (const int*)  d_in[4];
    const float* W1 = (const float*)d_in[5];
    const float* b1 = (const float*)d_in[6];
    const float* g1 = (const float*)d_in[7];
    const float* be1 = (const float*)d_in[8];
    const float* W2 = (const float*)d_in[9];
    const float* b2 = (const float*)d_in[10];
    const float* g2 = (const float*)d_in[11];
    const float* be2 = (const float*)d_in[12];
    const float* W3 = (const float*)d_in[13];
    const float* b3 = (const float*)d_in[14];
    const float* g3 = (const float*)d_in[15];
    const float* be3 = (const float*)d_in[16];
    float* out = (float*)d_out;

    float *buf0 = nullptr, *buf1 = nullptr;
    cudaGetSymbolAddress((void**)&buf0, g_buf0);
    cudaGetSymbolAddress((void**)&buf1, g_buf1);

    prep_kernel<<<12, THREADS, SMEM_P>>>(W1, W2, W3);

    const int nblk = NROWS / TROWS;   // 512
    layer_kernel<0><<<nblk, THREADS, SMEM_DYN>>>(
        nullptr, nullptr, s_feats, q_points, s_points, nbr_idx,
        b1, nullptr, nullptr, 0, buf0);
    layer_kernel<1><<<nblk, THREADS, SMEM_DYN>>>(
        buf0, nullptr, nullptr, nullptr, nullptr, nullptr,
        b2, g1, be1, 1, buf1);
    layer_kernel<2><<<nblk, THREADS, SMEM_DYN>>>(
        buf1, q_feats, nullptr, nullptr, nullptr, nullptr,
        b3, g2, be2, 2, buf0);
    finalize_kernel<<<(NROWS * CC / 4) / THREADS, THREADS>>>(buf0, g3, be3, out);
}

// round 14
// speedup vs baseline: 1.6283x; 1.6283x over previous
#include <cuda_runtime.h>
#include <cuda_bf16.h>
#include <cstdint>

// Problem constants
#define CC      128
#define GROUPS  8
#define NB      4
#define NN      8192
#define MM      32768
#define KNN     16
#define NROWS   (NB*NN)
#define TROWS   64                   // rows per CTA tile
#define THREADS 256
#define CNT_INV (1.0f/131072.0f)
#define APAD    136                  // padded bf16 row stride (272B -> conflict-free ldmatrix)

// layer-kernel smem: A tiles only
#define SM_AH   0
#define SM_AL   (TROWS*APAD*2)             // 17408
#define SMEM_DYN (2*TROWS*APAD*2)          // 34816

// prep smem: 64 n-rows x APAD bf16
#define SMEM_P  (64*APAD*2)                // 17408

// Scratch (device globals; no cudaMalloc allowed)
__device__ __align__(16) uint4 g_Wfrag[3][2][8][8][32];    // [layer][hi/lo][t][nb16][lane]
__device__ float g_sum[3][NB*GROUPS];
__device__ float g_sqs[3][NB*GROUPS];
__device__ float g_buf0[NROWS*CC];
__device__ float g_buf1[NROWS*CC];

// ---------------------------------------------------------------------------
// Helpers (all plain sm_80+ features; NO 'a'-gated instructions)
// ---------------------------------------------------------------------------
__device__ __forceinline__ uint32_t cvta_smem(const void* p) {
    uint32_t a;
    asm("{ .reg .u64 t; cvta.to.shared.u64 t, %1; cvt.u32.u64 %0, t; }"
        : "=r"(a) : "l"(p));
    return a;
}
__device__ __forceinline__ void ldmx4(uint32_t addr, uint32_t r[4]) {
    asm volatile("ldmatrix.sync.aligned.m8n8.x4.shared.b16 {%0,%1,%2,%3}, [%4];"
        : "=r"(r[0]), "=r"(r[1]), "=r"(r[2]), "=r"(r[3]) : "r"(addr));
}
// non-volatile: pure register op; lets ptxas schedule freely
__device__ __forceinline__ void mma16816(float d[4], const uint32_t a[4],
                                         uint32_t b0, uint32_t b1) {
    asm("mma.sync.aligned.m16n8k16.row.col.f32.bf16.bf16.f32 "
        "{%0,%1,%2,%3}, {%4,%5,%6,%7}, {%8,%9}, {%0,%1,%2,%3};"
        : "+f"(d[0]), "+f"(d[1]), "+f"(d[2]), "+f"(d[3])
        : "r"(a[0]), "r"(a[1]), "r"(a[2]), "r"(a[3]), "r"(b0), "r"(b1));
}
#define STS16(a, v) \
    asm volatile("st.shared.b16 [%0], %1;" :: "r"(a), "h"(v) : "memory")
#define STS64(a, x, y) \
    asm volatile("st.shared.v2.b32 [%0], {%1,%2};" :: "r"(a), "r"(x), "r"(y) : "memory")

__device__ __forceinline__ float leaky(float h) { return h >= 0.0f ? h : 0.1f * h; }

// split a float4 into hi/lo bf16x2 pairs and store to the A tiles
__device__ __forceinline__ void split_store(uint32_t sb, int r, int c4, float4 x) {
    __nv_bfloat16 h0 = __float2bfloat16(x.x);
    __nv_bfloat16 h1 = __float2bfloat16(x.y);
    __nv_bfloat16 h2 = __float2bfloat16(x.z);
    __nv_bfloat16 h3 = __float2bfloat16(x.w);
    __nv_bfloat16 l0 = __float2bfloat16(x.x - __bfloat162float(h0));
    __nv_bfloat16 l1 = __float2bfloat16(x.y - __bfloat162float(h1));
    __nv_bfloat16 l2 = __float2bfloat16(x.z - __bfloat162float(h2));
    __nv_bfloat16 l3 = __float2bfloat16(x.w - __bfloat162float(h3));
    uint32_t ha = (uint32_t)__bfloat16_as_ushort(h0) | ((uint32_t)__bfloat16_as_ushort(h1) << 16);
    uint32_t hb = (uint32_t)__bfloat16_as_ushort(h2) | ((uint32_t)__bfloat16_as_ushort(h3) << 16);
    uint32_t la = (uint32_t)__bfloat16_as_ushort(l0) | ((uint32_t)__bfloat16_as_ushort(l1) << 16);
    uint32_t lb = (uint32_t)__bfloat16_as_ushort(l2) | ((uint32_t)__bfloat16_as_ushort(l3) << 16);
    uint32_t off = (uint32_t)(r * APAD + c4) * 2;
    STS64(sb + SM_AH + off, ha, hb);
    STS64(sb + SM_AL + off, la, lb);
}

// ---------------------------------------------------------------------------
// prep: zero stats; block (l, h, nh) handles n in [nh*64, nh*64+64):
// split W^T into smem bf16 tile (float4 reads), fragmentize via the exact
// ldmatrix sequence the GEMM uses. 12 blocks.
// ---------------------------------------------------------------------------
__global__ void prep_kernel(const float* __restrict__ W1,
                            const float* __restrict__ W2,
                            const float* __restrict__ W3) {
    extern __shared__ __align__(16) char smem[];
    const int tid  = threadIdx.x;
    const int wid  = tid >> 5;
    const int lane = tid & 31;
    const int l  = blockIdx.x >> 2;
    const int h  = (blockIdx.x >> 1) & 1;
    const int nh = blockIdx.x & 1;          // which 64-col half of n
    const uint32_t sb = cvta_smem(smem);

    if (blockIdx.x == 0) {
        if (tid < 96)        { g_sum[tid / 32][tid % 32] = 0.0f; }
        else if (tid < 192)  { int u = tid - 96; g_sqs[u / 32][u % 32] = 0.0f; }
    }

    const float* W = (l == 0) ? W1 : ((l == 1) ? W2 : W3);

    // read W[k][n4] as float4 (n fast), split, scatter bf16 to smem[(n-nh*64)*APAD + k]
    #pragma unroll
    for (int t = 0; t < 8; t++) {
        int idx = tid + t * THREADS;       // 2048 float4 jobs
        int k   = idx >> 4;                // 16 float4 per 64-col half-row
        int n4  = (idx & 15) * 4 + nh * 64;
        float4 v = *(const float4*)&W[k * CC + n4];
        float vv[4] = {v.x, v.y, v.z, v.w};
        #pragma unroll
        for (int u = 0; u < 4; u++) {
            __nv_bfloat16 hi = __float2bfloat16(vv[u]);
            __nv_bfloat16 val = h == 0 ? hi
                              : __float2bfloat16(vv[u] - __bfloat162float(hi));
            STS16(sb + (uint32_t)((n4 + u - nh * 64) * APAD + k) * 2,
                  __bfloat16_as_ushort(val));
        }
    }
    __syncthreads();

    // 32 jobs: (t, nb_local 0..3); 4 per warp. Same lane addressing as the GEMM.
    const uint32_t lrow = (uint32_t)((lane & 7) + ((lane >> 4) << 3));
    const uint32_t lcol = (uint32_t)(lane & 8) << 1;
    #pragma unroll
    for (int i = 0; i < 4; i++) {
        int job = wid * 4 + i;
        int t   = job & 7;
        int nbl = job >> 3;                 // 0..3
        uint32_t addr = sb + (((uint32_t)(nbl * 16) + lrow) * APAD) * 2 + lcol
                      + (uint32_t)t * 32;
        uint32_t r[4];
        ldmx4(addr, r);
        g_Wfrag[l][h][t][nh * 4 + nbl][lane] = make_uint4(r[0], r[1], r[2], r[3]);
    }
}

// ---------------------------------------------------------------------------
// Fused layer kernel: 64-row tile, HMMA bf16 3-term-split GEMM.
// Stage-A loads are batched 4 rows at a time (MLP=4) so global-load latency
// is overlapped instead of serialized behind the volatile STS fence.
// MODE 0: x = IDW gather   MODE 1: x = leaky(GN(prev))   MODE 2: +resid
// ---------------------------------------------------------------------------
template <int MODE>
__global__ __launch_bounds__(THREADS, 4)
void layer_kernel(const float* __restrict__ in_y,
                  const float* __restrict__ resid,
                  const float* __restrict__ s_feats,
                  const float* __restrict__ q_points,
                  const float* __restrict__ s_points,
                  const int*   __restrict__ nbr_idx,
                  const float* __restrict__ bias,
                  const float* __restrict__ gamma_prev,
                  const float* __restrict__ beta_prev,
                  int layer,
                  float* __restrict__ out_y) {
    extern __shared__ __align__(16) char smem[];
    __shared__ float s_ms[GROUPS], s_rs[GROUPS];
    __shared__ float s_gb[2 * CC];
    __shared__ float s_gsum[GROUPS], s_gsqs[GROUPS];

    const int tid  = threadIdx.x;
    const int wid  = tid >> 5;
    const int lane = tid & 31;
    const int row0 = blockIdx.x * TROWS;
    const int b    = row0 >> 13;

    const uint32_t sb = cvta_smem(smem);

    if (tid < GROUPS) { s_gsum[tid] = 0.0f; s_gsqs[tid] = 0.0f; }

    if (MODE != 0) {
        if (tid < GROUPS) {
            float s  = g_sum[layer - 1][b * GROUPS + tid];
            float s2 = g_sqs[layer - 1][b * GROUPS + tid];
            float m  = s * CNT_INV;
            float v  = s2 * CNT_INV - m * m;
            s_ms[tid] = m;
            s_rs[tid] = rsqrtf(v + 1e-5f);
        }
        if (tid < CC) { s_gb[tid] = gamma_prev[tid]; s_gb[CC + tid] = beta_prev[tid]; }
        __syncthreads();
    }

    // ---- Stage A (batched): build x rows, split bf16 hi/lo, store ----
    if (MODE == 0) {
        const int c4 = lane * 4;
        #pragma unroll
        for (int grp = 0; grp < 2; grp++) {
            // phase 1: neighbor weights/ids for 4 rows (loads overlap, MLP~4)
            float wk4[4]; int id4[4]; float inv4[4];
            #pragma unroll
            for (int i = 0; i < 4; i++) {
                int it = grp * 4 + i;
                int r  = wid * 8 + it;
                int n    = (row0 + r) & (NN - 1);
                int base = b * NN + n;
                float qx = q_points[base * 3 + 0];
                float qy = q_points[base * 3 + 1];
                float qz = q_points[base * 3 + 2];
                float w = 0.0f; int id = 0;
                if (lane < KNN) {
                    const float* sp = s_points + ((size_t)base * KNN + lane) * 3;
                    float dx = sp[0] - qx, dy = sp[1] - qy, dz = sp[2] - qz;
                    w  = 1.0f / (dx * dx + dy * dy + dz * dz + 1e-8f);
                    id = nbr_idx[base * KNN + lane];
                }
                float wsum = w;
                #pragma unroll
                for (int o = 16; o > 0; o >>= 1)
                    wsum += __shfl_xor_sync(0xffffffffu, wsum, o);
                wk4[i] = w; id4[i] = id; inv4[i] = 1.0f / wsum;
            }
            // phase 2: gather + accumulate + store per row
            #pragma unroll
            for (int i = 0; i < 4; i++) {
                int it = grp * 4 + i;
                int r  = wid * 8 + it;
                float4 x = make_float4(0.f, 0.f, 0.f, 0.f);
                #pragma unroll
                for (int k = 0; k < KNN; k++) {
                    float wk  = __shfl_sync(0xffffffffu, wk4[i], k);
                    int   idk = __shfl_sync(0xffffffffu, id4[i], k);
                    const float4* fr = (const float4*)(s_feats + ((size_t)(b * MM + idk)) * CC);
                    float4 v = fr[lane];
                    x.x += wk * v.x; x.y += wk * v.y;
                    x.z += wk * v.z; x.w += wk * v.w;
                }
                x.x *= inv4[i]; x.y *= inv4[i]; x.z *= inv4[i]; x.w *= inv4[i];
                split_store(sb, r, c4, x);
            }
        }
    } else {
        #pragma unroll
        for (int grp = 0; grp < 2; grp++) {
            float4 xv[4], qv[4];
            int    rr[4], cc4[4];
            // phase 1: issue all loads (MLP 4 or 8)
            #pragma unroll
            for (int i = 0; i < 4; i++) {
                int f = tid + (grp * 4 + i) * THREADS;
                rr[i]  = f >> 5;
                cc4[i] = (f & 31) * 4;
                xv[i] = *(const float4*)&in_y[(size_t)(row0 + rr[i]) * CC + cc4[i]];
                if (MODE == 2)
                    qv[i] = *(const float4*)&resid[(size_t)(row0 + rr[i]) * CC + cc4[i]];
            }
            // phase 2: normalize + activate + split/store
            #pragma unroll
            for (int i = 0; i < 4; i++) {
                int c4 = cc4[i];
                int g  = c4 >> 4;
                float m = s_ms[g], rs = s_rs[g];
                float4 x;
                x.x = leaky((xv[i].x - m) * rs * s_gb[c4 + 0] + s_gb[CC + c4 + 0]);
                x.y = leaky((xv[i].y - m) * rs * s_gb[c4 + 1] + s_gb[CC + c4 + 1]);
                x.z = leaky((xv[i].z - m) * rs * s_gb[c4 + 2] + s_gb[CC + c4 + 2]);
                x.w = leaky((xv[i].w - m) * rs * s_gb[c4 + 3] + s_gb[CC + c4 + 3]);
                if (MODE == 2) {
                    x.x += qv[i].x; x.y += qv[i].y; x.z += qv[i].z; x.w += qv[i].w;
                }
                split_store(sb, rr[i], c4, x);
            }
        }
    }
    __syncthreads();

    // ---- HMMA GEMM: warp tile m16 x n64, 3-term split; B frags via LDG ----
    const int mbase = (wid & 3) * 16;
    const int nb0   = (wid >> 2) * 4;     // first n16 fragment index

    float acc[8][4];
    #pragma unroll
    for (int j = 0; j < 8; j++)
        #pragma unroll
        for (int q = 0; q < 4; q++) acc[j][q] = 0.0f;

    const uint32_t aoff = sb + SM_AH +
        (uint32_t)(((mbase + (lane & 15)) * APAD + ((lane >> 4) << 3)) << 1);

    const uint4* __restrict__ wfh = &g_Wfrag[layer][0][0][0][lane];
    const uint4* __restrict__ wfl = &g_Wfrag[layer][1][0][0][lane];

    #pragma unroll
    for (int t = 0; t < 8; t++) {
        const uint32_t ka = (uint32_t)t * 32;
        uint32_t ah[4], al[4];
        ldmx4(aoff + ka, ah);
        ldmx4(aoff + ka + SM_AL, al);
        #pragma unroll
        for (int p = 0; p < 4; p++) {
            const int fidx = (t * 8 + nb0 + p) * 32;
            uint4 bh = __ldg(wfh + fidx);
            uint4 bl = __ldg(wfl + fidx);
            float* a0 = acc[2 * p];
            float* a1 = acc[2 * p + 1];
            mma16816(a0, ah, bh.x, bh.y);
            mma16816(a1, ah, bh.z, bh.w);
            mma16816(a0, al, bh.x, bh.y);
            mma16816(a1, al, bh.z, bh.w);
            mma16816(a0, ah, bl.x, bl.y);
            mma16816(a1, ah, bl.z, bl.w);
        }
    }

    // ---- Epilogue: bias + store from fragments, warp-reduced stats ----
    {
        const int r0g   = row0 + mbase + (lane >> 2);
        const int nbase = (wid >> 2) * 64;
        #pragma unroll
        for (int gj = 0; gj < 4; gj++) {
            float s = 0.0f, s2 = 0.0f;
            #pragma unroll
            for (int jj = 0; jj < 2; jj++) {
                int j = 2 * gj + jj;
                int c = nbase + 8 * j + (lane & 3) * 2;
                float bb0 = __ldg(&bias[c]);
                float bb1 = __ldg(&bias[c + 1]);
                float y00 = acc[j][0] + bb0;
                float y01 = acc[j][1] + bb1;
                float y10 = acc[j][2] + bb0;
                float y11 = acc[j][3] + bb1;
                *(float2*)&out_y[(size_t)r0g * CC + c]       = make_float2(y00, y01);
                *(float2*)&out_y[(size_t)(r0g + 8) * CC + c] = make_float2(y10, y11);
                s  += y00 + y01 + y10 + y11;
                s2 += y00 * y00 + y01 * y01 + y10 * y10 + y11 * y11;
            }
            #pragma unroll
            for (int o = 16; o > 0; o >>= 1) {
                s  += __shfl_xor_sync(0xffffffffu, s,  o);
                s2 += __shfl_xor_sync(0xffffffffu, s2, o);
            }
            if (lane == 0) {
                int g = (nbase >> 4) + gj;
                atomicAdd(&s_gsum[g], s);
                atomicAdd(&s_gsqs[g], s2);
            }
        }
    }
    __syncthreads();
    if (tid < GROUPS) {
        atomicAdd(&g_sum[layer][b * GROUPS + tid], s_gsum[tid]);
        atomicAdd(&g_sqs[layer][b * GROUPS + tid], s_gsqs[tid]);
    }
}

// ---------------------------------------------------------------------------
// Finalize: out = leaky(GN3(y3))
// ---------------------------------------------------------------------------
__global__ void finalize_kernel(const float* __restrict__ in_y,
                                const float* __restrict__ gamma,
                                const float* __restrict__ beta,
                                float* __restrict__ out) {
    int f  = blockIdx.x * blockDim.x + threadIdx.x;
    int e  = f * 4;
    int c4 = e & (CC - 1);
    int row = e >> 7;
    int b  = row >> 13;
    int g  = c4 >> 4;
    float s  = g_sum[2][b * GROUPS + g];
    float s2 = g_sqs[2][b * GROUPS + g];
    float m  = s * CNT_INV;
    float v  = s2 * CNT_INV - m * m;
    float rs = rsqrtf(v + 1e-5f);
    float4 x = *(const float4*)&in_y[e];
    float4 o;
    o.x = leaky((x.x - m) * rs * gamma[c4 + 0] + beta[c4 + 0]);
    o.y = leaky((x.y - m) * rs * gamma[c4 + 1] + beta[c4 + 1]);
    o.z = leaky((x.z - m) * rs * gamma[c4 + 2] + beta[c4 + 2]);
    o.w = leaky((x.w - m) * rs * gamma[c4 + 3] + beta[c4 + 3]);
    *(float4*)&out[e] = o;
}

// ---------------------------------------------------------------------------
extern "C" void kernel_launch(void* const* d_in, const int* in_sizes, int n_in,
                              void* d_out, int out_size) {
    const float* q_feats  = (const float*)d_in[0];
    const float* s_feats  = (const float*)d_in[1];
    const float* q_points = (const float*)d_in[2];
    const float* s_points = (const float*)d_in[3];
    const int*   nbr_idx  = (const int*)  d_in[4];
    const float* W1 = (const float*)d_in[5];
    const float* b1 = (const float*)d_in[6];
    const float* g1 = (const float*)d_in[7];
    const float* be1 = (const float*)d_in[8];
    const float* W2 = (const float*)d_in[9];
    const float* b2 = (const float*)d_in[10];
    const float* g2 = (const float*)d_in[11];
    const float* be2 = (const float*)d_in[12];
    const float* W3 = (const float*)d_in[13];
    const float* b3 = (const float*)d_in[14];
    const float* g3 = (const float*)d_in[15];
    const float* be3 = (const float*)d_in[16];
    float* out = (float*)d_out;

    float *buf0 = nullptr, *buf1 = nullptr;
    cudaGetSymbolAddress((void**)&buf0, g_buf0);
    cudaGetSymbolAddress((void**)&buf1, g_buf1);

    prep_kernel<<<12, THREADS, SMEM_P>>>(W1, W2, W3);

    const int nblk = NROWS / TROWS;   // 512
    layer_kernel<0><<<nblk, THREADS, SMEM_DYN>>>(
        nullptr, nullptr, s_feats, q_points, s_points, nbr_idx,
        b1, nullptr, nullptr, 0, buf0);
    layer_kernel<1><<<nblk, THREADS, SMEM_DYN>>>(
        buf0, nullptr, nullptr, nullptr, nullptr, nullptr,
        b2, g1, be1, 1, buf1);
    layer_kernel<2><<<nblk, THREADS, SMEM_DYN>>>(
        buf1, q_feats, nullptr, nullptr, nullptr, nullptr,
        b3, g2, be2, 2, buf0);
    finalize_kernel<<<(NROWS * CC / 4) / THREADS, THREADS>>>(buf0, g3, be3, out);
}

// round 15
// speedup vs baseline: 1.7020x; 1.0453x over previous
#include <cuda_runtime.h>
#include <cuda_bf16.h>
#include <cstdint>

// Problem constants
#define CC      128
#define GROUPS  8
#define NB      4
#define NN      8192
#define MM      32768
#define KNN     16
#define NROWS   (NB*NN)
#define TROWS   32                   // rows per CTA tile (half: finer wave granularity)
#define THREADS 256
#define CNT_INV (1.0f/131072.0f)
#define APAD    136                  // padded bf16 row stride (272B -> conflict-free ldmatrix)

// layer-kernel smem: A tiles only
#define SM_AH   0
#define SM_AL   (TROWS*APAD*2)             // 8704
#define SMEM_DYN (2*TROWS*APAD*2)          // 17408

// prep smem: 64 n-rows x APAD bf16
#define SMEM_P  (64*APAD*2)                // 17408

// Scratch (device globals; no cudaMalloc allowed)
__device__ __align__(16) uint4 g_Wfrag[3][2][8][8][32];    // [layer][hi/lo][t][nb16][lane]
__device__ float g_sum[3][NB*GROUPS];
__device__ float g_sqs[3][NB*GROUPS];
__device__ float g_buf0[NROWS*CC];
__device__ float g_buf1[NROWS*CC];

// ---------------------------------------------------------------------------
// Helpers (all plain sm_80+ features; NO 'a'-gated instructions)
// ---------------------------------------------------------------------------
__device__ __forceinline__ uint32_t cvta_smem(const void* p) {
    uint32_t a;
    asm("{ .reg .u64 t; cvta.to.shared.u64 t, %1; cvt.u32.u64 %0, t; }"
        : "=r"(a) : "l"(p));
    return a;
}
__device__ __forceinline__ void ldmx4(uint32_t addr, uint32_t r[4]) {
    asm volatile("ldmatrix.sync.aligned.m8n8.x4.shared.b16 {%0,%1,%2,%3}, [%4];"
        : "=r"(r[0]), "=r"(r[1]), "=r"(r[2]), "=r"(r[3]) : "r"(addr));
}
// non-volatile: pure register op; lets ptxas schedule freely
__device__ __forceinline__ void mma16816(float d[4], const uint32_t a[4],
                                         uint32_t b0, uint32_t b1) {
    asm("mma.sync.aligned.m16n8k16.row.col.f32.bf16.bf16.f32 "
        "{%0,%1,%2,%3}, {%4,%5,%6,%7}, {%8,%9}, {%0,%1,%2,%3};"
        : "+f"(d[0]), "+f"(d[1]), "+f"(d[2]), "+f"(d[3])
        : "r"(a[0]), "r"(a[1]), "r"(a[2]), "r"(a[3]), "r"(b0), "r"(b1));
}
#define STS16(a, v) \
    asm volatile("st.shared.b16 [%0], %1;" :: "r"(a), "h"(v) : "memory")
#define STS64(a, x, y) \
    asm volatile("st.shared.v2.b32 [%0], {%1,%2};" :: "r"(a), "r"(x), "r"(y) : "memory")

__device__ __forceinline__ float leaky(float h) { return h >= 0.0f ? h : 0.1f * h; }

// split a float4 into hi/lo bf16x2 pairs and store to the A tiles
__device__ __forceinline__ void split_store(uint32_t sb, int r, int c4, float4 x) {
    __nv_bfloat16 h0 = __float2bfloat16(x.x);
    __nv_bfloat16 h1 = __float2bfloat16(x.y);
    __nv_bfloat16 h2 = __float2bfloat16(x.z);
    __nv_bfloat16 h3 = __float2bfloat16(x.w);
    __nv_bfloat16 l0 = __float2bfloat16(x.x - __bfloat162float(h0));
    __nv_bfloat16 l1 = __float2bfloat16(x.y - __bfloat162float(h1));
    __nv_bfloat16 l2 = __float2bfloat16(x.z - __bfloat162float(h2));
    __nv_bfloat16 l3 = __float2bfloat16(x.w - __bfloat162float(h3));
    uint32_t ha = (uint32_t)__bfloat16_as_ushort(h0) | ((uint32_t)__bfloat16_as_ushort(h1) << 16);
    uint32_t hb = (uint32_t)__bfloat16_as_ushort(h2) | ((uint32_t)__bfloat16_as_ushort(h3) << 16);
    uint32_t la = (uint32_t)__bfloat16_as_ushort(l0) | ((uint32_t)__bfloat16_as_ushort(l1) << 16);
    uint32_t lb = (uint32_t)__bfloat16_as_ushort(l2) | ((uint32_t)__bfloat16_as_ushort(l3) << 16);
    uint32_t off = (uint32_t)(r * APAD + c4) * 2;
    STS64(sb + SM_AH + off, ha, hb);
    STS64(sb + SM_AL + off, la, lb);
}

// ---------------------------------------------------------------------------
// prep: zero stats; block (l, h, nh) handles n in [nh*64, nh*64+64):
// split W^T into smem bf16 tile (float4 reads), fragmentize via the exact
// ldmatrix sequence the GEMM uses. 12 blocks.
// ---------------------------------------------------------------------------
__global__ void prep_kernel(const float* __restrict__ W1,
                            const float* __restrict__ W2,
                            const float* __restrict__ W3) {
    extern __shared__ __align__(16) char smem[];
    const int tid  = threadIdx.x;
    const int wid  = tid >> 5;
    const int lane = tid & 31;
    const int l  = blockIdx.x >> 2;
    const int h  = (blockIdx.x >> 1) & 1;
    const int nh = blockIdx.x & 1;          // which 64-col half of n
    const uint32_t sb = cvta_smem(smem);

    if (blockIdx.x == 0) {
        if (tid < 96)        { g_sum[tid / 32][tid % 32] = 0.0f; }
        else if (tid < 192)  { int u = tid - 96; g_sqs[u / 32][u % 32] = 0.0f; }
    }

    const float* W = (l == 0) ? W1 : ((l == 1) ? W2 : W3);

    // read W[k][n4] as float4 (n fast), split, scatter bf16 to smem[(n-nh*64)*APAD + k]
    #pragma unroll
    for (int t = 0; t < 8; t++) {
        int idx = tid + t * THREADS;       // 2048 float4 jobs
        int k   = idx >> 4;                // 16 float4 per 64-col half-row
        int n4  = (idx & 15) * 4 + nh * 64;
        float4 v = *(const float4*)&W[k * CC + n4];
        float vv[4] = {v.x, v.y, v.z, v.w};
        #pragma unroll
        for (int u = 0; u < 4; u++) {
            __nv_bfloat16 hi = __float2bfloat16(vv[u]);
            __nv_bfloat16 val = h == 0 ? hi
                              : __float2bfloat16(vv[u] - __bfloat162float(hi));
            STS16(sb + (uint32_t)((n4 + u - nh * 64) * APAD + k) * 2,
                  __bfloat16_as_ushort(val));
        }
    }
    __syncthreads();

    // 32 jobs: (t, nb_local 0..3); 4 per warp. Same lane addressing as the GEMM.
    const uint32_t lrow = (uint32_t)((lane & 7) + ((lane >> 4) << 3));
    const uint32_t lcol = (uint32_t)(lane & 8) << 1;
    #pragma unroll
    for (int i = 0; i < 4; i++) {
        int job = wid * 4 + i;
        int t   = job & 7;
        int nbl = job >> 3;                 // 0..3
        uint32_t addr = sb + (((uint32_t)(nbl * 16) + lrow) * APAD) * 2 + lcol
                      + (uint32_t)t * 32;
        uint32_t r[4];
        ldmx4(addr, r);
        g_Wfrag[l][h][t][nh * 4 + nbl][lane] = make_uint4(r[0], r[1], r[2], r[3]);
    }
}

// ---------------------------------------------------------------------------
// Fused layer kernel: 32-row tile, HMMA bf16 3-term-split GEMM.
// Warp tile m16 x n32 (pair = wid&1, quarter = wid>>1). Grid is ~2 waves so
// CTA phases de-align across the SM -> memory and tensor pipes overlap.
// MODE 0: x = IDW gather   MODE 1: x = leaky(GN(prev))   MODE 2: +resid
// ---------------------------------------------------------------------------
template <int MODE>
__global__ __launch_bounds__(THREADS, 4)
void layer_kernel(const float* __restrict__ in_y,
                  const float* __restrict__ resid,
                  const float* __restrict__ s_feats,
                  const float* __restrict__ q_points,
                  const float* __restrict__ s_points,
                  const int*   __restrict__ nbr_idx,
                  const float* __restrict__ bias,
                  const float* __restrict__ gamma_prev,
                  const float* __restrict__ beta_prev,
                  int layer,
                  float* __restrict__ out_y) {
    extern __shared__ __align__(16) char smem[];
    __shared__ float s_ms[GROUPS], s_rs[GROUPS];
    __shared__ float s_gb[2 * CC];
    __shared__ float s_gsum[GROUPS], s_gsqs[GROUPS];

    const int tid  = threadIdx.x;
    const int wid  = tid >> 5;
    const int lane = tid & 31;
    const int row0 = blockIdx.x * TROWS;
    const int b    = row0 >> 13;

    const uint32_t sb = cvta_smem(smem);

    if (tid < GROUPS) { s_gsum[tid] = 0.0f; s_gsqs[tid] = 0.0f; }

    if (MODE != 0) {
        if (tid < GROUPS) {
            float s  = g_sum[layer - 1][b * GROUPS + tid];
            float s2 = g_sqs[layer - 1][b * GROUPS + tid];
            float m  = s * CNT_INV;
            float v  = s2 * CNT_INV - m * m;
            s_ms[tid] = m;
            s_rs[tid] = rsqrtf(v + 1e-5f);
        }
        if (tid < CC) { s_gb[tid] = gamma_prev[tid]; s_gb[CC + tid] = beta_prev[tid]; }
        __syncthreads();
    }

    // ---- Stage A (batched): build x rows, split bf16 hi/lo, store ----
    if (MODE == 0) {
        const int c4 = lane * 4;
        // phase 1: neighbor weights/ids for the warp's 4 rows (loads overlap)
        float wk4[4]; int id4[4]; float inv4[4];
        #pragma unroll
        for (int i = 0; i < 4; i++) {
            int r  = wid * 4 + i;
            int n    = (row0 + r) & (NN - 1);
            int base = b * NN + n;
            float qx = q_points[base * 3 + 0];
            float qy = q_points[base * 3 + 1];
            float qz = q_points[base * 3 + 2];
            float w = 0.0f; int id = 0;
            if (lane < KNN) {
                const float* sp = s_points + ((size_t)base * KNN + lane) * 3;
                float dx = sp[0] - qx, dy = sp[1] - qy, dz = sp[2] - qz;
                w  = 1.0f / (dx * dx + dy * dy + dz * dz + 1e-8f);
                id = nbr_idx[base * KNN + lane];
            }
            float wsum = w;
            #pragma unroll
            for (int o = 16; o > 0; o >>= 1)
                wsum += __shfl_xor_sync(0xffffffffu, wsum, o);
            wk4[i] = w; id4[i] = id; inv4[i] = 1.0f / wsum;
        }
        // phase 2: gather + accumulate + store per row
        #pragma unroll
        for (int i = 0; i < 4; i++) {
            int r = wid * 4 + i;
            float4 x = make_float4(0.f, 0.f, 0.f, 0.f);
            #pragma unroll
            for (int k = 0; k < KNN; k++) {
                float wk  = __shfl_sync(0xffffffffu, wk4[i], k);
                int   idk = __shfl_sync(0xffffffffu, id4[i], k);
                const float4* fr = (const float4*)(s_feats + ((size_t)(b * MM + idk)) * CC);
                float4 v = fr[lane];
                x.x += wk * v.x; x.y += wk * v.y;
                x.z += wk * v.z; x.w += wk * v.w;
            }
            x.x *= inv4[i]; x.y *= inv4[i]; x.z *= inv4[i]; x.w *= inv4[i];
            split_store(sb, r, c4, x);
        }
    } else {
        float4 xv[4], qv[4];
        int    rr[4], cc4[4];
        // phase 1: issue all loads (MLP 4 or 8)
        #pragma unroll
        for (int i = 0; i < 4; i++) {
            int f = tid + i * THREADS;        // 1024 col-quads in tile
            rr[i]  = f >> 5;
            cc4[i] = (f & 31) * 4;
            xv[i] = *(const float4*)&in_y[(size_t)(row0 + rr[i]) * CC + cc4[i]];
            if (MODE == 2)
                qv[i] = *(const float4*)&resid[(size_t)(row0 + rr[i]) * CC + cc4[i]];
        }
        // phase 2: normalize + activate + split/store
        #pragma unroll
        for (int i = 0; i < 4; i++) {
            int c4 = cc4[i];
            int g  = c4 >> 4;
            float m = s_ms[g], rs = s_rs[g];
            float4 x;
            x.x = leaky((xv[i].x - m) * rs * s_gb[c4 + 0] + s_gb[CC + c4 + 0]);
            x.y = leaky((xv[i].y - m) * rs * s_gb[c4 + 1] + s_gb[CC + c4 + 1]);
            x.z = leaky((xv[i].z - m) * rs * s_gb[c4 + 2] + s_gb[CC + c4 + 2]);
            x.w = leaky((xv[i].w - m) * rs * s_gb[c4 + 3] + s_gb[CC + c4 + 3]);
            if (MODE == 2) {
                x.x += qv[i].x; x.y += qv[i].y; x.z += qv[i].z; x.w += qv[i].w;
            }
            split_store(sb, rr[i], c4, x);
        }
    }
    __syncthreads();

    // ---- HMMA GEMM: warp tile m16 x n32, 3-term split; B frags via LDG ----
    const int pair = wid & 1;             // m-strip (0..1)
    const int q    = wid >> 1;            // n-quarter (0..3)
    const int mbase = pair * 16;
    const int nb0   = q * 2;              // first n16 fragment index

    float acc[4][4];
    #pragma unroll
    for (int j = 0; j < 4; j++)
        #pragma unroll
        for (int u = 0; u < 4; u++) acc[j][u] = 0.0f;

    const uint32_t aoff = sb + SM_AH +
        (uint32_t)(((mbase + (lane & 15)) * APAD + ((lane >> 4) << 3)) << 1);

    const uint4* __restrict__ wfh = &g_Wfrag[layer][0][0][0][lane];
    const uint4* __restrict__ wfl = &g_Wfrag[layer][1][0][0][lane];

    #pragma unroll
    for (int t = 0; t < 8; t++) {
        const uint32_t ka = (uint32_t)t * 32;
        uint32_t ah[4], al[4];
        ldmx4(aoff + ka, ah);
        ldmx4(aoff + ka + SM_AL, al);
        #pragma unroll
        for (int p = 0; p < 2; p++) {
            const int fidx = (t * 8 + nb0 + p) * 32;
            uint4 bh = __ldg(wfh + fidx);
            uint4 bl = __ldg(wfl + fidx);
            float* a0 = acc[2 * p];
            float* a1 = acc[2 * p + 1];
            mma16816(a0, ah, bh.x, bh.y);
            mma16816(a1, ah, bh.z, bh.w);
            mma16816(a0, al, bh.x, bh.y);
            mma16816(a1, al, bh.z, bh.w);
            mma16816(a0, ah, bl.x, bl.y);
            mma16816(a1, ah, bl.z, bl.w);
        }
    }

    // ---- Epilogue: bias + store from fragments, warp-reduced stats ----
    {
        const int r0g   = row0 + mbase + (lane >> 2);
        const int nbase = q * 32;
        #pragma unroll
        for (int gj = 0; gj < 2; gj++) {
            float s = 0.0f, s2 = 0.0f;
            #pragma unroll
            for (int jj = 0; jj < 2; jj++) {
                int j = 2 * gj + jj;
                int c = nbase + 8 * j + (lane & 3) * 2;
                float bb0 = __ldg(&bias[c]);
                float bb1 = __ldg(&bias[c + 1]);
                float y00 = acc[j][0] + bb0;
                float y01 = acc[j][1] + bb1;
                float y10 = acc[j][2] + bb0;
                float y11 = acc[j][3] + bb1;
                *(float2*)&out_y[(size_t)r0g * CC + c]       = make_float2(y00, y01);
                *(float2*)&out_y[(size_t)(r0g + 8) * CC + c] = make_float2(y10, y11);
                s  += y00 + y01 + y10 + y11;
                s2 += y00 * y00 + y01 * y01 + y10 * y10 + y11 * y11;
            }
            #pragma unroll
            for (int o = 16; o > 0; o >>= 1) {
                s  += __shfl_xor_sync(0xffffffffu, s,  o);
                s2 += __shfl_xor_sync(0xffffffffu, s2, o);
            }
            if (lane == 0) {
                int g = (nbase >> 4) + gj;
                atomicAdd(&s_gsum[g], s);
                atomicAdd(&s_gsqs[g], s2);
            }
        }
    }
    __syncthreads();
    if (tid < GROUPS) {
        atomicAdd(&g_sum[layer][b * GROUPS + tid], s_gsum[tid]);
        atomicAdd(&g_sqs[layer][b * GROUPS + tid], s_gsqs[tid]);
    }
}

// ---------------------------------------------------------------------------
// Finalize: out = leaky(GN3(y3))
// ---------------------------------------------------------------------------
__global__ void finalize_kernel(const float* __restrict__ in_y,
                                const float* __restrict__ gamma,
                                const float* __restrict__ beta,
                                float* __restrict__ out) {
    int f  = blockIdx.x * blockDim.x + threadIdx.x;
    int e  = f * 4;
    int c4 = e & (CC - 1);
    int row = e >> 7;
    int b  = row >> 13;
    int g  = c4 >> 4;
    float s  = g_sum[2][b * GROUPS + g];
    float s2 = g_sqs[2][b * GROUPS + g];
    float m  = s * CNT_INV;
    float v  = s2 * CNT_INV - m * m;
    float rs = rsqrtf(v + 1e-5f);
    float4 x = *(const float4*)&in_y[e];
    float4 o;
    o.x = leaky((x.x - m) * rs * gamma[c4 + 0] + beta[c4 + 0]);
    o.y = leaky((x.y - m) * rs * gamma[c4 + 1] + beta[c4 + 1]);
    o.z = leaky((x.z - m) * rs * gamma[c4 + 2] + beta[c4 + 2]);
    o.w = leaky((x.w - m) * rs * gamma[c4 + 3] + beta[c4 + 3]);
    *(float4*)&out[e] = o;
}

// ---------------------------------------------------------------------------
extern "C" void kernel_launch(void* const* d_in, const int* in_sizes, int n_in,
                              void* d_out, int out_size) {
    const float* q_feats  = (const float*)d_in[0];
    const float* s_feats  = (const float*)d_in[1];
    const float* q_points = (const float*)d_in[2];
    const float* s_points = (const float*)d_in[3];
    const int*   nbr_idx  = (const int*)  d_in[4];
    const float* W1 = (const float*)d_in[5];
    const float* b1 = (const float*)d_in[6];
    const float* g1 = (const float*)d_in[7];
    const float* be1 = (const float*)d_in[8];
    const float* W2 = (const float*)d_in[9];
    const float* b2 = (const float*)d_in[10];
    const float* g2 = (const float*)d_in[11];
    const float* be2 = (const float*)d_in[12];
    const float* W3 = (const float*)d_in[13];
    const float* b3 = (const float*)d_in[14];
    const float* g3 = (const float*)d_in[15];
    const float* be3 = (const float*)d_in[16];
    float* out = (float*)d_out;

    float *buf0 = nullptr, *buf1 = nullptr;
    cudaGetSymbolAddress((void**)&buf0, g_buf0);
    cudaGetSymbolAddress((void**)&buf1, g_buf1);

    prep_kernel<<<12, THREADS, SMEM_P>>>(W1, W2, W3);

    const int nblk = NROWS / TROWS;   // 1024
    layer_kernel<0><<<nblk, THREADS, SMEM_DYN>>>(
        nullptr, nullptr, s_feats, q_points, s_points, nbr_idx,
        b1, nullptr, nullptr, 0, buf0);
    layer_kernel<1><<<nblk, THREADS, SMEM_DYN>>>(
        buf0, nullptr, nullptr, nullptr, nullptr, nullptr,
        b2, g1, be1, 1, buf1);
    layer_kernel<2><<<nblk, THREADS, SMEM_DYN>>>(
        buf1, q_feats, nullptr, nullptr, nullptr, nullptr,
        b3, g2, be2, 2, buf0);
    finalize_kernel<<<(NROWS * CC / 4) / THREADS, THREADS>>>(buf0, g3, be3, out);
}